// round 4
// baseline (speedup 1.0000x reference)
#include <cuda_runtime.h>
#include <cuda_fp16.h>
#include <float.h>

typedef unsigned long long U64;

// ---------------- scratch ----------------
__device__ float g_cand0[10 * 128 * 5];   // [target][spatialCTA][5]
__device__ float g_cand1[5 * 64 * 5];     // [target][CTA][5]
__device__ int   g_count;                 // zero-init; self-reset each run

// ---------------- f32x2 helpers (scale-1 path) ----------------
__device__ __forceinline__ U64 add2(U64 a, U64 b) {
    U64 r; asm("add.rn.f32x2 %0, %1, %2;" : "=l"(r) : "l"(a), "l"(b)); return r;
}
__device__ __forceinline__ U64 pack2(float lo, float hi) {
    U64 r; asm("mov.b64 %0, {%1, %2};" : "=l"(r) : "f"(lo), "f"(hi)); return r;
}
__device__ __forceinline__ float2 unpack2(U64 v) {
    float lo, hi; asm("mov.b64 {%0, %1}, %2;" : "=f"(lo), "=f"(hi) : "l"(v));
    return make_float2(lo, hi);
}
#define ABS2_MASK 0x7FFFFFFF7FFFFFFFULL

// ---------------- sorted-5 insert ----------------
__device__ __forceinline__ void ins5(float& a0, float& a1, float& a2, float& a3,
                                     float& a4, float v)
{
    if (v < a4) {
        a4 = v; float t;
        if (a4 < a3) { t = a3; a3 = a4; a4 = t; }
        if (a3 < a2) { t = a2; a2 = a3; a3 = t; }
        if (a2 < a1) { t = a1; a1 = a2; a2 = t; }
        if (a1 < a0) { t = a0; a0 = a1; a1 = t; }
    }
}

// 256-thread tree reduce of sorted-5 lists held in registers; result in tid 0.
__device__ __forceinline__ void tree5(float* sm, int tid,
                                      float& a0, float& a1, float& a2,
                                      float& a3, float& a4)
{
    sm[tid * 5 + 0] = a0; sm[tid * 5 + 1] = a1; sm[tid * 5 + 2] = a2;
    sm[tid * 5 + 3] = a3; sm[tid * 5 + 4] = a4;
    __syncthreads();
    for (int stride = 128; stride > 0; stride >>= 1) {
        if (tid < stride) {
            const float* o = &sm[(tid + stride) * 5];
#pragma unroll
            for (int k = 0; k < 5; k++) ins5(a0, a1, a2, a3, a4, o[k]);
            sm[tid * 5 + 0] = a0; sm[tid * 5 + 1] = a1; sm[tid * 5 + 2] = a2;
            sm[tid * 5 + 3] = a3; sm[tid * 5 + 4] = a4;
        }
        __syncthreads();
    }
}

// =====================================================================
// Single fused kernel. grid = (8, 16, 6), 256 threads.
//   z in 0..4 : scale0 (C=64,H=W=256,ps=3,Hm=253), targets 2z, 2z+1
//   z == 5    : scale1 (C=128,H=W=128,ps=1,Hm=127), flat CTA < 64
// Last CTA (atomic count over 704) merges per-CTA top-5 candidates.
// =====================================================================
#define TILE_W 32
#define TILE_H 16
#define SM_W 34
#define SM_H 18
#define SM_N (SM_W * SM_H)   // 612
#define NCTA_TOTAL 704

__global__ __launch_bounds__(256, 4) void fused_kernel(
    const float* __restrict__ src0, const float* __restrict__ tgt0,
    const int* __restrict__ pos0,
    const float* __restrict__ src1, const float* __restrict__ tgt1,
    const int* __restrict__ pos1,
    float* __restrict__ out)
{
    __shared__ __half2 s_negt[32 * 2 * 12];   // [cp][T][12 pad] (scale0)
    __shared__ __half2 s_tile[2][SM_N];       // double-buffered src tile (fp16x2)
    __shared__ U64     s_negt1[64 * 5];       // scale1 target table (f32x2)
    __shared__ float   s_top[256 * 5];
    __shared__ int     s_last;

    const int tid = threadIdx.x;
    const int bz  = blockIdx.z;

    if (bz == 5) {
        // ------------------------- scale 1 -------------------------
        const int flat = blockIdx.y * 8 + blockIdx.x;
        if (flat >= 64) return;

        for (int i = tid; i < 64 * 5; i += 256) {
            int T = i % 5, cp = i / 5;
            int th = pos1[T * 2 + 0], tw = pos1[T * 2 + 1];
            const float* b = tgt1 + th * 128 + tw;
            s_negt1[i] = pack2(-b[(2 * cp) * 16384], -b[(2 * cp + 1) * 16384]);
        }
        __syncthreads();

        const int p  = flat * 256 + tid;
        const int pc = p < 16129 ? p : 16128;
        const int h = pc / 127, w = pc - h * 127;
        const float* sp = src1 + h * 128 + w;

        U64 acc[5];
#pragma unroll
        for (int T = 0; T < 5; T++) acc[T] = 0ULL;

        for (int cp = 0; cp < 64; cp++) {
            U64 s = pack2(sp[(2 * cp) * 16384], sp[(2 * cp + 1) * 16384]);
#pragma unroll
            for (int T = 0; T < 5; T++) {
                U64 d = add2(s, s_negt1[cp * 5 + T]) & ABS2_MASK;
                acc[T] = add2(acc[T], d);
            }
        }

#pragma unroll
        for (int T = 0; T < 5; T++) {
            float2 a = unpack2(acc[T]);
            float v = (p < 16129) ? (a.x + a.y) : FLT_MAX;
            float a0 = v, a1 = FLT_MAX, a2 = FLT_MAX, a3 = FLT_MAX, a4 = FLT_MAX;
            tree5(s_top, tid, a0, a1, a2, a3, a4);
            if (tid == 0) {
                float* c = g_cand1 + (T * 64 + flat) * 5;
                c[0] = a0; c[1] = a1; c[2] = a2; c[3] = a3; c[4] = a4;
            }
        }
    } else {
        // ------------------------- scale 0 -------------------------
        const int tx = blockIdx.x * TILE_W;
        const int ty = blockIdx.y * TILE_H;
        const int sx = blockIdx.y * 8 + blockIdx.x;   // spatial CTA id 0..127

        // target patch table, fp16x2 (ch pair), padded stride 12
        for (int i = tid; i < 32 * 2 * 9; i += 256) {
            int cp = i / 18, rem = i % 18;
            int T = rem / 9, o = rem % 9;
            int tg = 2 * bz + T;
            int th = pos0[tg * 2 + 0], tw = pos0[tg * 2 + 1];
            int di = o / 3, dj = o % 3;
            const float* b = tgt0 + (th + di) * 256 + (tw + dj);
            s_negt[(cp * 2 + T) * 12 + o] =
                __floats2half2_rn(b[(2 * cp) * 65536], b[(2 * cp + 1) * 65536]);
        }

        // fill-slot precompute
        int  goff[3];
        bool gval[3];
#pragma unroll
        for (int k = 0; k < 3; k++) {
            int i = tid + k * 256;
            int r = i / SM_W, c = i - r * SM_W;
            int y = ty + r, x = tx + c;
            gval[k] = (i < SM_N) && (y < 256) && (x < 256);
            goff[k] = y * 256 + x;
        }

        __half2 pre[3];
        {   // prologue: cp = 0
#pragma unroll
            for (int k = 0; k < 3; k++)
                pre[k] = gval[k] ? __floats2half2_rn(src0[goff[k]], src0[goff[k] + 65536])
                                 : __half2half2(__float2half(0.f));
#pragma unroll
            for (int k = 0; k < 3; k++) {
                int i = tid + k * 256;
                if (i < SM_N) s_tile[0][i] = pre[k];
            }
        }
        __syncthreads();

        const int thx = tid & 31;
        const int thy = tid >> 5;
        const int w  = tx + thx;
        const int h0 = ty + 2 * thy;
        const bool act0 = (w < 253) && (h0 < 253);
        const bool act1 = (w < 253) && (h0 + 1 < 253);
        const int r0 = 2 * thy;

        float acc0[2] = {0.f, 0.f}, acc1[2] = {0.f, 0.f};

        for (int cp = 0; cp < 32; cp++) {
            // prefetch next channel pair
            if (cp + 1 < 32) {
                const float* s = src0 + (2 * (cp + 1)) * 65536;
#pragma unroll
                for (int k = 0; k < 3; k++)
                    pre[k] = gval[k] ? __floats2half2_rn(s[goff[k]], s[goff[k] + 65536])
                                     : __half2half2(__float2half(0.f));
            }

            const __half2* buf = s_tile[cp & 1];
            __half2 sv[4][3];
#pragma unroll
            for (int r = 0; r < 4; r++)
#pragma unroll
                for (int j = 0; j < 3; j++)
                    sv[r][j] = buf[(r0 + r) * SM_W + thx + j];

#pragma unroll
            for (int T = 0; T < 2; T++) {
                const __half2* tp = s_negt + (cp * 2 + T) * 12;
                __half2 tv[9];
#pragma unroll
                for (int o = 0; o < 9; o++) tv[o] = tp[o];

                __half2 hA = __half2half2(__float2half(0.f));
                __half2 hB = hA;
#pragma unroll
                for (int o = 0; o < 9; o++) {
                    const int di = o / 3, dj = o % 3;
                    hA = __hadd2(hA, __habs2(__hsub2(sv[di][dj],     tv[o])));
                    hB = __hadd2(hB, __habs2(__hsub2(sv[di + 1][dj], tv[o])));
                }
                float2 fA = __half22float2(hA);
                float2 fB = __half22float2(hB);
                acc0[T] += fA.x + fA.y;
                acc1[T] += fB.x + fB.y;
            }

            if (cp + 1 < 32) {
                __half2* nb = s_tile[(cp + 1) & 1];
#pragma unroll
                for (int k = 0; k < 3; k++) {
                    int i = tid + k * 256;
                    if (i < SM_N) nb[i] = pre[k];
                }
                __syncthreads();
            }
        }

        // per-CTA top-5 per target
#pragma unroll
        for (int T = 0; T < 2; T++) {
            float v0 = act0 ? acc0[T] : FLT_MAX;
            float v1 = act1 ? acc1[T] : FLT_MAX;
            float a0 = fminf(v0, v1), a1 = fmaxf(v0, v1);
            float a2 = FLT_MAX, a3 = FLT_MAX, a4 = FLT_MAX;
            tree5(s_top, tid, a0, a1, a2, a3, a4);
            if (tid == 0) {
                float* c = g_cand0 + ((2 * bz + T) * 128 + sx) * 5;
                c[0] = a0; c[1] = a1; c[2] = a2; c[3] = a3; c[4] = a4;
            }
        }
    }

    // --------------- last-CTA merge + finalize ---------------
    if (tid == 0) {
        __threadfence();
        int old = atomicAdd(&g_count, 1);
        s_last = (old == NCTA_TOTAL - 1);
        if (s_last) g_count = 0;            // reset for next replay
    }
    __syncthreads();
    if (!s_last) return;
    __threadfence();                         // see all candidates

    float total = 0.f;
    for (int t = 0; t < 15; t++) {
        const float* d;
        int n; float scale;
        if (t < 10) { d = g_cand0 + t * 640;        n = 640; scale = 1.0f / (576.0f * 50.0f); }
        else        { d = g_cand1 + (t - 10) * 320; n = 320; scale = 1.0f / (128.0f * 50.0f); }

        float a0 = FLT_MAX, a1 = FLT_MAX, a2 = FLT_MAX, a3 = FLT_MAX, a4 = FLT_MAX;
        for (int i = tid; i < n; i += 256)
            ins5(a0, a1, a2, a3, a4, d[i]);
        tree5(s_top, tid, a0, a1, a2, a3, a4);
        if (tid == 0) total += (a0 + a1 + a2 + a3 + a4) * scale;
        __syncthreads();
    }
    if (tid == 0) out[0] = total;
}

// =====================================================================
extern "C" void kernel_launch(void* const* d_in, const int* in_sizes, int n_in,
                              void* d_out, int out_size)
{
    const float* src0 = (const float*)d_in[0];
    const float* tgt0 = (const float*)d_in[1];
    const float* src1 = (const float*)d_in[2];
    const float* tgt1 = (const float*)d_in[3];
    const int*   pos0 = (const int*)d_in[4];
    const int*   pos1 = (const int*)d_in[5];

    dim3 g(8, 16, 6);
    fused_kernel<<<g, 256>>>(src0, tgt0, pos0, src1, tgt1, pos1, (float*)d_out);
}